// round 12
// baseline (speedup 1.0000x reference)
#include <cuda_runtime.h>
#include <cuda_fp16.h>

// HashEmbedding: out[t, d] = sum_{h=0..3} weight_table[x[t,h] + 513*h] * emb_table[x[t,h]>>1][d]
// x is int32.
// R12: R11 structure (pre-converted tables, bulk-copy prologue, sync-free pair-ILP
// loop) with the arithmetic rebuilt around fp16:
//   - gathers as LDS.128 (lane owns 8 contiguous cols; 8 loads/pair vs 16)
//   - weights pre-duplicated as half2 (1 LDS.32 broadcast each, no cvt)
//   - HFMA2 accumulation in fp16; only the 4 final half2 accs per token are
//     converted to f32 for the store. ~2x fewer loop instructions than R11.

#define NUM_HASHES 4
#define D 256
#define W_TABLE 2052           // 512*4 + 4
#define EMB_ROWS 256
#define BLOCK_THREADS 1024
#define WARPS_PER_BLOCK (BLOCK_THREADS / 32)
#define GRID_X 148

#define W_BYTES   (W_TABLE * 4)          // 8208 (half2 per entry)
#define EMB_BYTES (EMB_ROWS * D * 2)     // 131072

// smem byte offsets
#define OFF_W     0                      // half2[2052]
#define OFF_MBAR  8208                   // 8-byte aligned
#define OFF_EMB   8320                   // 128-aligned
#define SMEM_BYTES (OFF_EMB + EMB_BYTES) // 139392

// Pre-converted tables (filled by convert kernel each replay).
__device__ __align__(16) __half2 g_wh2[W_TABLE];
__device__ __align__(16) __half2 g_emb_h2[EMB_ROWS * D / 2];

__global__ void convert_tables_kernel(const float* __restrict__ weight_table,
                                      const float* __restrict__ emb_table)
{
    const int i = blockIdx.x * blockDim.x + threadIdx.x;
    if (i < W_TABLE) {
        g_wh2[i] = __float2half2_rn(weight_table[i]);   // duplicated lanes
    }
    if (i < EMB_ROWS * D / 2) {
        const float2 v = *reinterpret_cast<const float2*>(emb_table + i * 2);
        g_emb_h2[i] = __floats2half2_rn(v.x, v.y);
    }
}

__global__ __launch_bounds__(BLOCK_THREADS, 1)
void hash_embedding_kernel(const int* __restrict__ x,
                           float* __restrict__ out,
                           int ntok)
{
    extern __shared__ char smem[];
    const __half2* s_wh  = reinterpret_cast<const __half2*>(smem + OFF_W);
    const char*    s_emb = smem + OFF_EMB;   // [256 rows][256 halves] = 512 B/row

    const int tid = threadIdx.x;

    unsigned int smem_base;
    asm("{ .reg .u64 t; cvta.to.shared.u64 t, %1; cvt.u32.u64 %0, t; }"
        : "=r"(smem_base) : "l"(smem));

    // ---- async bulk-load both pre-converted tables (one thread, one mbarrier) ----
    if (tid == 0) {
        asm volatile("mbarrier.init.shared.b64 [%0], 1;"
                     :: "r"(smem_base + OFF_MBAR) : "memory");
        asm volatile("fence.proxy.async.shared::cta;" ::: "memory");
        asm volatile("mbarrier.arrive.expect_tx.shared.b64 _, [%0], %1;"
                     :: "r"(smem_base + OFF_MBAR),
                        "r"((unsigned)(W_BYTES + EMB_BYTES)) : "memory");
        asm volatile(
            "cp.async.bulk.shared::cta.global.mbarrier::complete_tx::bytes "
            "[%0], [%1], %2, [%3];"
            :: "r"(smem_base + OFF_W), "l"(g_wh2),
               "r"((unsigned)W_BYTES), "r"(smem_base + OFF_MBAR) : "memory");
        asm volatile(
            "cp.async.bulk.shared::cta.global.mbarrier::complete_tx::bytes "
            "[%0], [%1], %2, [%3];"
            :: "r"(smem_base + OFF_EMB), "l"(g_emb_h2),
               "r"((unsigned)EMB_BYTES), "r"(smem_base + OFF_MBAR) : "memory");
    }
    __syncthreads();   // mbarrier init visible to all before waiting

    {
        unsigned int mbar = smem_base + OFF_MBAR;
        unsigned int done;
        asm volatile(
            "{\n\t.reg .pred p;\n\t"
            "mbarrier.try_wait.parity.acquire.cta.shared::cta.b64 p, [%1], 0;\n\t"
            "selp.b32 %0, 1, 0, p;\n\t}"
            : "=r"(done) : "r"(mbar) : "memory");
        if (!done) {
            asm volatile(
                "{\n\t.reg .pred P1;\n\t"
                "WL_%=:\n\t"
                "mbarrier.try_wait.parity.acquire.cta.shared::cta.b64 P1, [%0], 0, 0x989680;\n\t"
                "@P1 bra.uni WD_%=;\n\t"
                "bra.uni WL_%=;\n\t"
                "WD_%=:\n\t}"
                :: "r"(mbar) : "memory");
        }
    }

    const int lane = tid & 31;
    const int gw   = blockIdx.x * WARPS_PER_BLOCK + (tid >> 5);
    const int nw   = GRID_X * WARPS_PER_BLOCK;     // 4736 warps

    const int off = lane * 16;          // lane owns cols [lane*8, lane*8+8) -> 16 B

    const int npairs = ntok >> 1;       // 32768

    int p = gw;
    if (p >= npairs) return;

    int4 xi0 = *reinterpret_cast<const int4*>(x + (long long)(2 * p)     * NUM_HASHES);
    int4 xi1 = *reinterpret_cast<const int4*>(x + (long long)(2 * p + 1) * NUM_HASHES);

    #pragma unroll 1
    for (; p < npairs; p += nw) {
        const int pn = (p + nw < npairs) ? (p + nw) : p;
        const int4 xn0 = *reinterpret_cast<const int4*>(x + (long long)(2 * pn)     * NUM_HASHES);
        const int4 xn1 = *reinterpret_cast<const int4*>(x + (long long)(2 * pn + 1) * NUM_HASHES);

        // per-sample weights as duplicated half2 (LDS.32 broadcast, no cvt)
        const __half2 u0 = s_wh[xi0.x];
        const __half2 u1 = s_wh[xi0.y + 513];
        const __half2 u2 = s_wh[xi0.z + 1026];
        const __half2 u3 = s_wh[xi0.w + 1539];
        const __half2 v0 = s_wh[xi1.x];
        const __half2 v1 = s_wh[xi1.y + 513];
        const __half2 v2 = s_wh[xi1.z + 1026];
        const __half2 v3 = s_wh[xi1.w + 1539];

        // fp16 row bases (idx = x >> 1; 512 B per row)
        const char* p00 = s_emb + ((xi0.x >> 1) << 9);
        const char* p01 = s_emb + ((xi0.y >> 1) << 9);
        const char* p02 = s_emb + ((xi0.z >> 1) << 9);
        const char* p03 = s_emb + ((xi0.w >> 1) << 9);
        const char* p10 = s_emb + ((xi1.x >> 1) << 9);
        const char* p11 = s_emb + ((xi1.y >> 1) << 9);
        const char* p12 = s_emb + ((xi1.z >> 1) << 9);
        const char* p13 = s_emb + ((xi1.w >> 1) << 9);

        // 8 batched LDS.128 gathers (conflict-free: each 8-lane phase = 128 B)
        const uint4 e00 = *reinterpret_cast<const uint4*>(p00 + off);
        const uint4 e01 = *reinterpret_cast<const uint4*>(p01 + off);
        const uint4 e02 = *reinterpret_cast<const uint4*>(p02 + off);
        const uint4 e03 = *reinterpret_cast<const uint4*>(p03 + off);
        const uint4 e10 = *reinterpret_cast<const uint4*>(p10 + off);
        const uint4 e11 = *reinterpret_cast<const uint4*>(p11 + off);
        const uint4 e12 = *reinterpret_cast<const uint4*>(p12 + off);
        const uint4 e13 = *reinterpret_cast<const uint4*>(p13 + off);

        const __half2* h00 = reinterpret_cast<const __half2*>(&e00);
        const __half2* h01 = reinterpret_cast<const __half2*>(&e01);
        const __half2* h02 = reinterpret_cast<const __half2*>(&e02);
        const __half2* h03 = reinterpret_cast<const __half2*>(&e03);
        const __half2* h10 = reinterpret_cast<const __half2*>(&e10);
        const __half2* h11 = reinterpret_cast<const __half2*>(&e11);
        const __half2* h12 = reinterpret_cast<const __half2*>(&e12);
        const __half2* h13 = reinterpret_cast<const __half2*>(&e13);

        float2 f0[4], f1[4];
        #pragma unroll
        for (int s = 0; s < 4; ++s) {
            __half2 a = __hmul2(h00[s], u0);
            a = __hfma2(h01[s], u1, a);
            a = __hfma2(h02[s], u2, a);
            a = __hfma2(h03[s], u3, a);
            f0[s] = __half22float2(a);

            __half2 b = __hmul2(h10[s], v0);
            b = __hfma2(h11[s], v1, b);
            b = __hfma2(h12[s], v2, b);
            b = __hfma2(h13[s], v3, b);
            f1[s] = __half22float2(b);
        }

        // stores: lane covers cols [lane*8, lane*8+8) -> two float4 per token
        float* op = out + (long long)(2 * p) * D + lane * 8;
        *reinterpret_cast<float4*>(op)           = make_float4(f0[0].x, f0[0].y, f0[1].x, f0[1].y);
        *reinterpret_cast<float4*>(op + 4)       = make_float4(f0[2].x, f0[2].y, f0[3].x, f0[3].y);
        *reinterpret_cast<float4*>(op + 256)     = make_float4(f1[0].x, f1[0].y, f1[1].x, f1[1].y);
        *reinterpret_cast<float4*>(op + 260)     = make_float4(f1[2].x, f1[2].y, f1[3].x, f1[3].y);

        xi0 = xn0;
        xi1 = xn1;
    }
}

extern "C" void kernel_launch(void* const* d_in, const int* in_sizes, int n_in,
                              void* d_out, int out_size)
{
    const int*   x            = (const int*)d_in[0];
    const float* weight_table = (const float*)d_in[1];
    const float* emb_table    = (const float*)d_in[2];
    float*       out          = (float*)d_out;

    const int ntok = in_sizes[0] / NUM_HASHES;   // 65536

    // 1) pre-convert both tables (covers max(2052, 32768) indices)
    convert_tables_kernel<<<(EMB_ROWS * D / 2 + 255) / 256, 256>>>(weight_table, emb_table);

    // 2) main kernel
    cudaFuncSetAttribute(hash_embedding_kernel,
                         cudaFuncAttributeMaxDynamicSharedMemorySize, SMEM_BYTES);
    hash_embedding_kernel<<<GRID_X, BLOCK_THREADS, SMEM_BYTES>>>(x, out, ntok);
}

// round 13
// speedup vs baseline: 1.5038x; 1.5038x over previous
#include <cuda_runtime.h>
#include <cuda_fp16.h>

// HashEmbedding: out[t, d] = sum_{h=0..3} weight_table[x[t,h] + 513*h] * emb_table[x[t,h]>>1][d]
// x is int32.
// R13: R11 memory structure UNCHANGED (pre-converted fp16 table, bulk-copy
// prologue, 16 LDS.64 gathers, fully coalesced float4 stores, sync-free
// pair-ILP loop) + R12's arithmetic only: half2 duplicated weights (LDS.32
// broadcast) and HFMA2 accumulation. R12 proved the math is accurate enough
// (rel_err 4.4e-4) but its strided stores wrecked L1/L2 - reverted here.

#define NUM_HASHES 4
#define D 256
#define W_TABLE 2052           // 512*4 + 4
#define EMB_ROWS 256
#define BLOCK_THREADS 1024
#define WARPS_PER_BLOCK (BLOCK_THREADS / 32)
#define GRID_X 148

#define W_BYTES   (W_TABLE * 4)          // 8208 (half2 per entry)
#define EMB_BYTES (EMB_ROWS * D * 2)     // 131072

// smem byte offsets
#define OFF_W     0                      // half2[2052]
#define OFF_MBAR  8208
#define OFF_EMB   8320                   // 128-aligned
#define SMEM_BYTES (OFF_EMB + EMB_BYTES)

// Pre-converted tables (filled by convert kernel each replay).
__device__ __align__(16) __half2 g_wh2[W_TABLE];
__device__ __align__(16) __half2 g_emb_h2[EMB_ROWS * D / 2];

__global__ void convert_tables_kernel(const float* __restrict__ weight_table,
                                      const float* __restrict__ emb_table)
{
    const int i = blockIdx.x * blockDim.x + threadIdx.x;
    if (i < W_TABLE) {
        g_wh2[i] = __float2half2_rn(weight_table[i]);   // duplicated lanes
    }
    if (i < EMB_ROWS * D / 2) {
        const float2 v = *reinterpret_cast<const float2*>(emb_table + i * 2);
        g_emb_h2[i] = __floats2half2_rn(v.x, v.y);
    }
}

__global__ __launch_bounds__(BLOCK_THREADS, 1)
void hash_embedding_kernel(const int* __restrict__ x,
                           float* __restrict__ out,
                           int ntok)
{
    extern __shared__ char smem[];
    const __half2* s_wh  = reinterpret_cast<const __half2*>(smem + OFF_W);
    const char*    s_emb = smem + OFF_EMB;   // [256 rows][256 halves] = 512 B/row

    const int tid = threadIdx.x;

    unsigned int smem_base;
    asm("{ .reg .u64 t; cvta.to.shared.u64 t, %1; cvt.u32.u64 %0, t; }"
        : "=r"(smem_base) : "l"(smem));

    // ---- async bulk-load both pre-converted tables ----
    if (tid == 0) {
        asm volatile("mbarrier.init.shared.b64 [%0], 1;"
                     :: "r"(smem_base + OFF_MBAR) : "memory");
        asm volatile("fence.proxy.async.shared::cta;" ::: "memory");
        asm volatile("mbarrier.arrive.expect_tx.shared.b64 _, [%0], %1;"
                     :: "r"(smem_base + OFF_MBAR),
                        "r"((unsigned)(W_BYTES + EMB_BYTES)) : "memory");
        asm volatile(
            "cp.async.bulk.shared::cta.global.mbarrier::complete_tx::bytes "
            "[%0], [%1], %2, [%3];"
            :: "r"(smem_base + OFF_W), "l"(g_wh2),
               "r"((unsigned)W_BYTES), "r"(smem_base + OFF_MBAR) : "memory");
        asm volatile(
            "cp.async.bulk.shared::cta.global.mbarrier::complete_tx::bytes "
            "[%0], [%1], %2, [%3];"
            :: "r"(smem_base + OFF_EMB), "l"(g_emb_h2),
               "r"((unsigned)EMB_BYTES), "r"(smem_base + OFF_MBAR) : "memory");
    }
    __syncthreads();   // mbarrier init visible to all before waiting

    {
        unsigned int mbar = smem_base + OFF_MBAR;
        unsigned int done;
        asm volatile(
            "{\n\t.reg .pred p;\n\t"
            "mbarrier.try_wait.parity.acquire.cta.shared::cta.b64 p, [%1], 0;\n\t"
            "selp.b32 %0, 1, 0, p;\n\t}"
            : "=r"(done) : "r"(mbar) : "memory");
        if (!done) {
            asm volatile(
                "{\n\t.reg .pred P1;\n\t"
                "WL_%=:\n\t"
                "mbarrier.try_wait.parity.acquire.cta.shared::cta.b64 P1, [%0], 0, 0x989680;\n\t"
                "@P1 bra.uni WD_%=;\n\t"
                "bra.uni WL_%=;\n\t"
                "WD_%=:\n\t}"
                :: "r"(mbar) : "memory");
        }
    }

    const int lane = tid & 31;
    const int gw   = blockIdx.x * WARPS_PER_BLOCK + (tid >> 5);
    const int nw   = GRID_X * WARPS_PER_BLOCK;     // 4736 warps

    const int offA = lane * 8;          // cols [lane*4 .. lane*4+3]   (8 B fp16)
    const int offB = 256 + lane * 8;    // cols [128+lane*4 .. +3]

    const int npairs = ntok >> 1;       // 32768

    int p = gw;
    if (p >= npairs) return;

    int4 xi0 = *reinterpret_cast<const int4*>(x + (long long)(2 * p)     * NUM_HASHES);
    int4 xi1 = *reinterpret_cast<const int4*>(x + (long long)(2 * p + 1) * NUM_HASHES);

    #pragma unroll 1
    for (; p < npairs; p += nw) {
        const int pn = (p + nw < npairs) ? (p + nw) : p;
        const int4 xn0 = *reinterpret_cast<const int4*>(x + (long long)(2 * pn)     * NUM_HASHES);
        const int4 xn1 = *reinterpret_cast<const int4*>(x + (long long)(2 * pn + 1) * NUM_HASHES);

        // per-sample weights as duplicated half2 (LDS.32 broadcast, no cvt)
        const __half2 u0 = s_wh[xi0.x];
        const __half2 u1 = s_wh[xi0.y + 513];
        const __half2 u2 = s_wh[xi0.z + 1026];
        const __half2 u3 = s_wh[xi0.w + 1539];
        const __half2 v0 = s_wh[xi1.x];
        const __half2 v1 = s_wh[xi1.y + 513];
        const __half2 v2 = s_wh[xi1.z + 1026];
        const __half2 v3 = s_wh[xi1.w + 1539];

        // fp16 row bases (idx = x >> 1; 512 B per row)
        const char* p00 = s_emb + ((xi0.x >> 1) << 9);
        const char* p01 = s_emb + ((xi0.y >> 1) << 9);
        const char* p02 = s_emb + ((xi0.z >> 1) << 9);
        const char* p03 = s_emb + ((xi0.w >> 1) << 9);
        const char* p10 = s_emb + ((xi1.x >> 1) << 9);
        const char* p11 = s_emb + ((xi1.y >> 1) << 9);
        const char* p12 = s_emb + ((xi1.z >> 1) << 9);
        const char* p13 = s_emb + ((xi1.w >> 1) << 9);

        // batch all 16 gather loads (LDS.64, conflict-free)
        uint2 gA0 = *reinterpret_cast<const uint2*>(p00 + offA);
        uint2 gA1 = *reinterpret_cast<const uint2*>(p01 + offA);
        uint2 gA2 = *reinterpret_cast<const uint2*>(p02 + offA);
        uint2 gA3 = *reinterpret_cast<const uint2*>(p03 + offA);
        uint2 hA0 = *reinterpret_cast<const uint2*>(p10 + offA);
        uint2 hA1 = *reinterpret_cast<const uint2*>(p11 + offA);
        uint2 hA2 = *reinterpret_cast<const uint2*>(p12 + offA);
        uint2 hA3 = *reinterpret_cast<const uint2*>(p13 + offA);
        uint2 gB0 = *reinterpret_cast<const uint2*>(p00 + offB);
        uint2 gB1 = *reinterpret_cast<const uint2*>(p01 + offB);
        uint2 gB2 = *reinterpret_cast<const uint2*>(p02 + offB);
        uint2 gB3 = *reinterpret_cast<const uint2*>(p03 + offB);
        uint2 hB0 = *reinterpret_cast<const uint2*>(p10 + offB);
        uint2 hB1 = *reinterpret_cast<const uint2*>(p11 + offB);
        uint2 hB2 = *reinterpret_cast<const uint2*>(p12 + offB);
        uint2 hB3 = *reinterpret_cast<const uint2*>(p13 + offB);

        #define H2(u) (*reinterpret_cast<const __half2*>(&(u)))

        // token0 half A: accumulate 2 half2 (cols lane*4 .. lane*4+3)
        __half2 aAx = __hmul2(H2(gA0.x), u0);
        __half2 aAy = __hmul2(H2(gA0.y), u0);
        aAx = __hfma2(H2(gA1.x), u1, aAx);  aAy = __hfma2(H2(gA1.y), u1, aAy);
        aAx = __hfma2(H2(gA2.x), u2, aAx);  aAy = __hfma2(H2(gA2.y), u2, aAy);
        aAx = __hfma2(H2(gA3.x), u3, aAx);  aAy = __hfma2(H2(gA3.y), u3, aAy);

        // token0 half B
        __half2 aBx = __hmul2(H2(gB0.x), u0);
        __half2 aBy = __hmul2(H2(gB0.y), u0);
        aBx = __hfma2(H2(gB1.x), u1, aBx);  aBy = __hfma2(H2(gB1.y), u1, aBy);
        aBx = __hfma2(H2(gB2.x), u2, aBx);  aBy = __hfma2(H2(gB2.y), u2, aBy);
        aBx = __hfma2(H2(gB3.x), u3, aBx);  aBy = __hfma2(H2(gB3.y), u3, aBy);

        // token1 half A
        __half2 bAx = __hmul2(H2(hA0.x), v0);
        __half2 bAy = __hmul2(H2(hA0.y), v0);
        bAx = __hfma2(H2(hA1.x), v1, bAx);  bAy = __hfma2(H2(hA1.y), v1, bAy);
        bAx = __hfma2(H2(hA2.x), v2, bAx);  bAy = __hfma2(H2(hA2.y), v2, bAy);
        bAx = __hfma2(H2(hA3.x), v3, bAx);  bAy = __hfma2(H2(hA3.y), v3, bAy);

        // token1 half B
        __half2 bBx = __hmul2(H2(hB0.x), v0);
        __half2 bBy = __hmul2(H2(hB0.y), v0);
        bBx = __hfma2(H2(hB1.x), v1, bBx);  bBy = __hfma2(H2(hB1.y), v1, bBy);
        bBx = __hfma2(H2(hB2.x), v2, bBx);  bBy = __hfma2(H2(hB2.y), v2, bBy);
        bBx = __hfma2(H2(hB3.x), v3, bBx);  bBy = __hfma2(H2(hB3.y), v3, bBy);

        #undef H2

        const float2 fA0 = __half22float2(aAx), fA1 = __half22float2(aAy);
        const float2 fB0 = __half22float2(aBx), fB1 = __half22float2(aBy);
        const float2 gA  = __half22float2(bAx), gA1f = __half22float2(bAy);
        const float2 gB  = __half22float2(bBx), gB1f = __half22float2(bBy);

        // coalesced stores: lane L writes cols [L*4, L*4+4) of each 128-col half
        float* op = out + (long long)(2 * p) * D + lane * 4;
        *reinterpret_cast<float4*>(op)       = make_float4(fA0.x, fA0.y, fA1.x, fA1.y);
        *reinterpret_cast<float4*>(op + 128) = make_float4(fB0.x, fB0.y, fB1.x, fB1.y);
        *reinterpret_cast<float4*>(op + 256) = make_float4(gA.x,  gA.y,  gA1f.x, gA1f.y);
        *reinterpret_cast<float4*>(op + 384) = make_float4(gB.x,  gB.y,  gB1f.x, gB1f.y);

        xi0 = xn0;
        xi1 = xn1;
    }
}

extern "C" void kernel_launch(void* const* d_in, const int* in_sizes, int n_in,
                              void* d_out, int out_size)
{
    const int*   x            = (const int*)d_in[0];
    const float* weight_table = (const float*)d_in[1];
    const float* emb_table    = (const float*)d_in[2];
    float*       out          = (float*)d_out;

    const int ntok = in_sizes[0] / NUM_HASHES;   // 65536

    convert_tables_kernel<<<(EMB_ROWS * D / 2 + 255) / 256, 256>>>(weight_table, emb_table);

    cudaFuncSetAttribute(hash_embedding_kernel,
                         cudaFuncAttributeMaxDynamicSharedMemorySize, SMEM_BYTES);
    hash_embedding_kernel<<<GRID_X, BLOCK_THREADS, SMEM_BYTES>>>(x, out, ntok);
}